// round 4
// baseline (speedup 1.0000x reference)
#include <cuda_runtime.h>

#define BB 512
#define SS 512
#define DD 512
#define LN_EPS 1e-5f
#define INV_SCALE 0.125f   // 1/sqrt(64)

// ---------------- scratch ----------------
__device__ float d_LNs[BB*DD];    // LN(sentiment)
__device__ float d_Wqk[DD*DD];    // Wq @ Wk^T
__device__ float d_u[BB*DD];      // LNs @ Wqk + wb
__device__ float d_gqk[BB*DD];    // g_kv * u / 8
__device__ float d_c1[BB];
__device__ float d_c2[BB];
__device__ float d_LNa[BB*DD];    // attn-weighted LN_kv vector
__device__ float d_Wvo[DD*DD];    // Wv @ Wo
__device__ float d_Wvg[DD*DD];    // Wvo @ WgB
__device__ float d_bvo[DD];       // bv @ Wo + bo
__device__ float d_bvg[DD];       // bg + bvo @ WgB
__device__ float d_ctxo[BB*DD];   // context after Wo
__device__ float d_G[BB*DD];      // gate pre-activation
__device__ float d_wb[DD];        // bq @ Wk^T
__device__ float d_wqbk[DD];      // Wq @ bk
__device__ float d_bqbk;          // bq . bk

// ---------------- block reductions (128 threads) ----------------
__device__ __forceinline__ void bred2_128(float& a, float& b) {
#pragma unroll
    for (int o = 16; o; o >>= 1) {
        a += __shfl_xor_sync(0xffffffffu, a, o);
        b += __shfl_xor_sync(0xffffffffu, b, o);
    }
    __shared__ float sa[4], sb[4];
    int w = threadIdx.x >> 5;
    if ((threadIdx.x & 31) == 0) { sa[w] = a; sb[w] = b; }
    __syncthreads();
    a = sa[0] + sa[1] + sa[2] + sa[3];
    b = sb[0] + sb[1] + sb[2] + sb[3];
}

__device__ __forceinline__ void bred3_128(float& a, float& b, float& c) {
#pragma unroll
    for (int o = 16; o; o >>= 1) {
        a += __shfl_xor_sync(0xffffffffu, a, o);
        b += __shfl_xor_sync(0xffffffffu, b, o);
        c += __shfl_xor_sync(0xffffffffu, c, o);
    }
    __shared__ float sa[4], sb[4], sc[4];
    int w = threadIdx.x >> 5;
    if ((threadIdx.x & 31) == 0) { sa[w] = a; sb[w] = b; sc[w] = c; }
    __syncthreads();
    a = sa[0] + sa[1] + sa[2] + sa[3];
    b = sb[0] + sb[1] + sb[2] + sb[3];
    c = sc[0] + sc[1] + sc[2] + sc[3];
}

// ---------------- LN of sentiment ----------------
__global__ void k_ln_sent(const float* __restrict__ sent,
                          const float* __restrict__ g, const float* __restrict__ be) {
    int b = blockIdx.x, t = threadIdx.x;
    const float4* row = (const float4*)(sent + (size_t)b * DD);
    float4 x = row[t];
    float s = x.x + x.y + x.z + x.w;
    float ss = fmaf(x.x, x.x, fmaf(x.y, x.y, fmaf(x.z, x.z, x.w * x.w)));
    bred2_128(s, ss);
    float m = s * (1.0f / DD);
    float var = ss * (1.0f / DD) - m * m;
    float r = rsqrtf(var + LN_EPS);
    float4 gg = ((const float4*)g)[t];
    float4 bb = ((const float4*)be)[t];
    float4 o;
    o.x = (x.x - m) * r * gg.x + bb.x;
    o.y = (x.y - m) * r * gg.y + bb.y;
    o.z = (x.z - m) * r * gg.z + bb.z;
    o.w = (x.w - m) * r * gg.w + bb.w;
    ((float4*)(d_LNs + (size_t)b * DD))[t] = o;
}

// ---------------- weight-side bias matvecs ----------------
__global__ void k_bias_prep(const float* __restrict__ Wk, const float* __restrict__ bq,
                            const float* __restrict__ Wq, const float* __restrict__ bk) {
    int e = blockIdx.x, t = threadIdx.x;
    float a = 0.f, b2 = 0.f, c = 0.f;
    for (int d = t; d < DD; d += 128) {
        a  = fmaf(Wk[(size_t)e * DD + d], bq[d], a);
        b2 = fmaf(Wq[(size_t)e * DD + d], bk[d], b2);
        c  = fmaf(bq[d], bk[d], c);
    }
    bred3_128(a, b2, c);
    if (t == 0) {
        d_wb[e] = a;
        d_wqbk[e] = b2;
        if (e == 0) d_bqbk = c;
    }
}

// ---------------- per-batch score constants ----------------
__global__ void k_prep(const float* __restrict__ g_kv, const float* __restrict__ beta_kv) {
    int b = blockIdx.x, t = threadIdx.x;
    float4 u4  = ((const float4*)(d_u   + (size_t)b * DD))[t];
    float4 ln4 = ((const float4*)(d_LNs + (size_t)b * DD))[t];
    float4 g4  = ((const float4*)g_kv)[t];
    float4 be4 = ((const float4*)beta_kv)[t];
    float4 wq4 = ((const float4*)d_wqbk)[t];
    float4 gq;
    gq.x = g4.x * u4.x * INV_SCALE;
    gq.y = g4.y * u4.y * INV_SCALE;
    gq.z = g4.z * u4.z * INV_SCALE;
    gq.w = g4.w * u4.w * INV_SCALE;
    ((float4*)(d_gqk + (size_t)b * DD))[t] = gq;
    float c1 = gq.x + gq.y + gq.z + gq.w;
    float c2 = fmaf(be4.x, u4.x, fmaf(be4.y, u4.y, fmaf(be4.z, u4.z, be4.w * u4.w)))
             + fmaf(ln4.x, wq4.x, fmaf(ln4.y, wq4.y, fmaf(ln4.z, wq4.z, ln4.w * wq4.w)));
    bred2_128(c1, c2);
    if (t == 0) {
        d_c1[b] = c1;
        d_c2[b] = (c2 + d_bqbk) * INV_SCALE;
    }
}

// ---------------- fused LN + scores + online softmax + weighted accum ----------------
__global__ void __launch_bounds__(256) k_attn(const float* __restrict__ price,
                                              const float* __restrict__ g_kv,
                                              const float* __restrict__ beta_kv,
                                              float* __restrict__ attn_out) {
    int b = blockIdx.x;
    int t = threadIdx.x, w = t >> 5, l = t & 31;

    __shared__ float s_sc[SS];
    __shared__ float s_wm[8], s_wz[8], s_wt[8];
    __shared__ float s_y[8][DD];

    const float4* gq4 = (const float4*)(d_gqk + (size_t)b * DD);
    float4 gq[4];
#pragma unroll
    for (int i = 0; i < 4; i++) gq[i] = gq4[l + 32 * i];
    const float c1 = d_c1[b], c2 = d_c2[b];

    float yac[4][4];
#pragma unroll
    for (int i = 0; i < 4; i++)
#pragma unroll
        for (int j = 0; j < 4; j++) yac[i][j] = 0.f;

    float M = -1e30f, Z = 0.f, T = 0.f;

    const float4* xr = (const float4*)(price + ((size_t)b * SS + (size_t)w * 64) * DD);
    float4 p0 = __ldcs(xr + l), p1 = __ldcs(xr + l + 32),
           p2 = __ldcs(xr + l + 64), p3 = __ldcs(xr + l + 96);

    for (int s = 0; s < 64; s++) {
        float4 x0 = p0, x1 = p1, x2 = p2, x3 = p3;
        if (s < 63) {
            xr += 128;   // next row (DD floats = 128 float4)
            p0 = __ldcs(xr + l);      p1 = __ldcs(xr + l + 32);
            p2 = __ldcs(xr + l + 64); p3 = __ldcs(xr + l + 96);
        }

        float sx = 0.f, sxx = 0.f, sxg = 0.f;
#define ACC4(v, g) do { \
        sx += v.x + v.y + v.z + v.w; \
        sxx = fmaf(v.x, v.x, fmaf(v.y, v.y, fmaf(v.z, v.z, fmaf(v.w, v.w, sxx)))); \
        sxg = fmaf(v.x, g.x, fmaf(v.y, g.y, fmaf(v.z, g.z, fmaf(v.w, g.w, sxg)))); } while (0)
        ACC4(x0, gq[0]); ACC4(x1, gq[1]); ACC4(x2, gq[2]); ACC4(x3, gq[3]);
#undef ACC4

#pragma unroll
        for (int o = 16; o; o >>= 1) {
            sx  += __shfl_xor_sync(0xffffffffu, sx, o);
            sxx += __shfl_xor_sync(0xffffffffu, sxx, o);
            sxg += __shfl_xor_sync(0xffffffffu, sxg, o);
        }
        float m = sx * (1.0f / DD);
        float var = sxx * (1.0f / DD) - m * m;
        float r = rsqrtf(var + LN_EPS);
        float sc = fmaf(r, sxg - m * c1, c2);
        if (l == 0) s_sc[w * 64 + s] = sc;

        float wgt;
        if (sc > M) {   // warp-uniform after butterfly
            float corr = __expf(M - sc);
            Z *= corr; T *= corr;
#pragma unroll
            for (int i = 0; i < 4; i++)
#pragma unroll
                for (int j = 0; j < 4; j++) yac[i][j] *= corr;
            M = sc;
            wgt = 1.0f;
        } else {
            wgt = __expf(sc - M);
        }
        Z += wgt;
        float cw = wgt * r;
        T = fmaf(cw, m, T);
        yac[0][0] = fmaf(cw, x0.x, yac[0][0]); yac[0][1] = fmaf(cw, x0.y, yac[0][1]);
        yac[0][2] = fmaf(cw, x0.z, yac[0][2]); yac[0][3] = fmaf(cw, x0.w, yac[0][3]);
        yac[1][0] = fmaf(cw, x1.x, yac[1][0]); yac[1][1] = fmaf(cw, x1.y, yac[1][1]);
        yac[1][2] = fmaf(cw, x1.z, yac[1][2]); yac[1][3] = fmaf(cw, x1.w, yac[1][3]);
        yac[2][0] = fmaf(cw, x2.x, yac[2][0]); yac[2][1] = fmaf(cw, x2.y, yac[2][1]);
        yac[2][2] = fmaf(cw, x2.z, yac[2][2]); yac[2][3] = fmaf(cw, x2.w, yac[2][3]);
        yac[3][0] = fmaf(cw, x3.x, yac[3][0]); yac[3][1] = fmaf(cw, x3.y, yac[3][1]);
        yac[3][2] = fmaf(cw, x3.z, yac[3][2]); yac[3][3] = fmaf(cw, x3.w, yac[3][3]);
    }

    if (l == 0) { s_wm[w] = M; s_wz[w] = Z; s_wt[w] = T; }
    __syncthreads();

    float gM = s_wm[0];
#pragma unroll
    for (int i = 1; i < 8; i++) gM = fmaxf(gM, s_wm[i]);
    float Zg = 0.f, Tg = 0.f;
#pragma unroll
    for (int i = 0; i < 8; i++) {
        float e = __expf(s_wm[i] - gM);
        Zg = fmaf(s_wz[i], e, Zg);
        Tg = fmaf(s_wt[i], e, Tg);
    }
    float myf = __expf(M - gM);
#pragma unroll
    for (int i = 0; i < 4; i++) {
        float4 v = make_float4(yac[i][0] * myf, yac[i][1] * myf, yac[i][2] * myf, yac[i][3] * myf);
        *(float4*)&s_y[w][4 * (l + 32 * i)] = v;
    }
    __syncthreads();

    float invZ = 1.0f / Zg;
    float tvv = Tg * invZ;
    for (int e = t; e < DD; e += 256) {
        float acc = 0.f;
#pragma unroll
        for (int w2 = 0; w2 < 8; w2++) acc += s_y[w2][e];
        d_LNa[(size_t)b * DD + e] = fmaf(g_kv[e], acc * invZ - tvv, beta_kv[e]);
    }
    for (int s = t; s < SS; s += 256)
        attn_out[(size_t)b * SS + s] = __expf(s_sc[s] - gM) * invZ;
}

// ---------------- bvo[d] = bo[d] + sum_e bv[e]*Wo[e,d] ----------------
__global__ void k_bvo(const float* __restrict__ bv, const float* __restrict__ bo,
                      const float* __restrict__ Wo) {
    int d = blockIdx.x * 128 + threadIdx.x;
    float a0 = 0.f, a1 = 0.f, a2 = 0.f, a3 = 0.f;
    for (int e = 0; e < DD; e += 4) {
        a0 = fmaf(bv[e + 0], Wo[(size_t)(e + 0) * DD + d], a0);
        a1 = fmaf(bv[e + 1], Wo[(size_t)(e + 1) * DD + d], a1);
        a2 = fmaf(bv[e + 2], Wo[(size_t)(e + 2) * DD + d], a2);
        a3 = fmaf(bv[e + 3], Wo[(size_t)(e + 3) * DD + d], a3);
    }
    d_bvo[d] = a0 + a1 + a2 + a3 + bo[d];
}

// ---------------- bvg[n] = bg[n] + sum_d bvo[d]*WgB[d,n] ----------------
__global__ void k_bvg(const float* __restrict__ bg, const float* __restrict__ WgB) {
    int n = blockIdx.x * 128 + threadIdx.x;
    float a0 = 0.f, a1 = 0.f, a2 = 0.f, a3 = 0.f;
    for (int d = 0; d < DD; d += 4) {
        a0 = fmaf(d_bvo[d + 0], WgB[(size_t)(d + 0) * DD + n], a0);
        a1 = fmaf(d_bvo[d + 1], WgB[(size_t)(d + 1) * DD + n], a1);
        a2 = fmaf(d_bvo[d + 2], WgB[(size_t)(d + 2) * DD + n], a2);
        a3 = fmaf(d_bvo[d + 3], WgB[(size_t)(d + 3) * DD + n], a3);
    }
    d_bvg[n] = a0 + a1 + a2 + a3 + bg[n];
}

// ---------------- fused = sigmoid(G)*(ctxo - sent) + sent ----------------
__global__ void k_fuse(const float* __restrict__ sent, float* __restrict__ out) {
    int i = blockIdx.x * 256 + threadIdx.x;
    float a = 1.0f / (1.0f + __expf(-d_G[i]));
    out[i] = fmaf(a, d_ctxo[i] - sent[i], sent[i]);
}

// ---------------- SGEMM: 32x64 tile, 128 threads, 4x4/thread, double-buffered ----------------
// All matrices 512x512. TRANSB: B stored [N,K].
// EPI: 0 = store; 1 = store + bias[col]; 2 = store + X1[row,col] (matrix add)
template <int TRANSB, int EPI>
__global__ void __launch_bounds__(128) k_gemm(const float* __restrict__ A,
                                              const float* __restrict__ Bm,
                                              const float* __restrict__ bias,
                                              float* __restrict__ C,
                                              const float* __restrict__ X1) {
    __shared__ float As[2][32][36];
    __shared__ float Bs[2][32][68];
    const int t = threadIdx.x;
    const int tx = t & 15, ty = t >> 4;
    const int m0 = blockIdx.y * 32, n0 = blockIdx.x * 64;

    const int arA = t >> 3, aq = t & 7;
    const float* Abase = A + (size_t)(m0 + arA) * DD + aq * 4;
    const int brB = t >> 4, bq = t & 15;
    const int nrB = t >> 3;
    const float* Bbase = TRANSB ? (Bm + (size_t)(n0 + nrB) * DD + aq * 4)
                                : (Bm + (size_t)brB * DD + n0 + bq * 4);

    float acc[4][4];
#pragma unroll
    for (int i = 0; i < 4; i++)
#pragma unroll
        for (int j = 0; j < 4; j++) acc[i][j] = 0.f;

    float4 aP[2], bP[4];

    aP[0] = *(const float4*)(Abase);
    aP[1] = *(const float4*)(Abase + 16 * DD);
#pragma unroll
    for (int i = 0; i < 4; i++)
        bP[i] = TRANSB ? *(const float4*)(Bbase + (size_t)(16 * i) * DD)
                       : *(const float4*)(Bbase + (size_t)(8 * i) * DD);

    {
        As[0][aq * 4 + 0][arA] = aP[0].x; As[0][aq * 4 + 1][arA] = aP[0].y;
        As[0][aq * 4 + 2][arA] = aP[0].z; As[0][aq * 4 + 3][arA] = aP[0].w;
        As[0][aq * 4 + 0][arA + 16] = aP[1].x; As[0][aq * 4 + 1][arA + 16] = aP[1].y;
        As[0][aq * 4 + 2][arA + 16] = aP[1].z; As[0][aq * 4 + 3][arA + 16] = aP[1].w;
        if (TRANSB) {
#pragma unroll
            for (int i = 0; i < 4; i++) {
                Bs[0][aq * 4 + 0][nrB + 16 * i] = bP[i].x;
                Bs[0][aq * 4 + 1][nrB + 16 * i] = bP[i].y;
                Bs[0][aq * 4 + 2][nrB + 16 * i] = bP[i].z;
                Bs[0][aq * 4 + 3][nrB + 16 * i] = bP[i].w;
            }
        } else {
#pragma unroll
            for (int i = 0; i < 4; i++)
                *(float4*)&Bs[0][brB + 8 * i][bq * 4] = bP[i];
        }
    }
    __syncthreads();

    int buf = 0;
#pragma unroll 1
    for (int kt = 0; kt < 16; kt++) {
        if (kt < 15) {
            int ko = (kt + 1) * 32;
            aP[0] = *(const float4*)(Abase + ko);
            aP[1] = *(const float4*)(Abase + 16 * DD + ko);
#pragma unroll
            for (int i = 0; i < 4; i++)
                bP[i] = TRANSB ? *(const float4*)(Bbase + (size_t)(16 * i) * DD + ko)
                               : *(const float4*)(Bbase + (size_t)(ko + 8 * i) * DD);
        }
#pragma unroll
        for (int k = 0; k < 32; k++) {
            float4 a4 = *(const float4*)&As[buf][k][ty * 4];
            float4 b4 = *(const float4*)&Bs[buf][k][tx * 4];
            float ar[4] = {a4.x, a4.y, a4.z, a4.w};
            float br[4] = {b4.x, b4.y, b4.z, b4.w};
#pragma unroll
            for (int i = 0; i < 4; i++)
#pragma unroll
                for (int j = 0; j < 4; j++) acc[i][j] = fmaf(ar[i], br[j], acc[i][j]);
        }
        if (kt < 15) {
            int nb = buf ^ 1;
            As[nb][aq * 4 + 0][arA] = aP[0].x; As[nb][aq * 4 + 1][arA] = aP[0].y;
            As[nb][aq * 4 + 2][arA] = aP[0].z; As[nb][aq * 4 + 3][arA] = aP[0].w;
            As[nb][aq * 4 + 0][arA + 16] = aP[1].x; As[nb][aq * 4 + 1][arA + 16] = aP[1].y;
            As[nb][aq * 4 + 2][arA + 16] = aP[1].z; As[nb][aq * 4 + 3][arA + 16] = aP[1].w;
            if (TRANSB) {
#pragma unroll
                for (int i = 0; i < 4; i++) {
                    Bs[nb][aq * 4 + 0][nrB + 16 * i] = bP[i].x;
                    Bs[nb][aq * 4 + 1][nrB + 16 * i] = bP[i].y;
                    Bs[nb][aq * 4 + 2][nrB + 16 * i] = bP[i].z;
                    Bs[nb][aq * 4 + 3][nrB + 16 * i] = bP[i].w;
                }
            } else {
#pragma unroll
                for (int i = 0; i < 4; i++)
                    *(float4*)&Bs[nb][brB + 8 * i][bq * 4] = bP[i];
            }
        }
        __syncthreads();
        buf ^= 1;
    }

#pragma unroll
    for (int i = 0; i < 4; i++) {
        int row = m0 + ty * 4 + i;
        float* cp = C + (size_t)row * DD + n0 + tx * 4;
        float4 v = make_float4(acc[i][0], acc[i][1], acc[i][2], acc[i][3]);
        if (EPI == 1) {
            const float* bp = bias + n0 + tx * 4;
            v.x += bp[0]; v.y += bp[1]; v.z += bp[2]; v.w += bp[3];
        }
        if (EPI == 2) {
            const float4 o = *(const float4*)(X1 + (size_t)row * DD + n0 + tx * 4);
            v.x += o.x; v.y += o.y; v.z += o.z; v.w += o.w;
        }
        *(float4*)cp = v;
    }
}

// ---------------- launch ----------------
extern "C" void kernel_launch(void* const* d_in, const int* in_sizes, int n_in,
                              void* d_out, int out_size) {
    const float* sent    = (const float*)d_in[0];
    const float* price   = (const float*)d_in[1];
    const float* Wq      = (const float*)d_in[2];
    const float* bq      = (const float*)d_in[3];
    const float* Wk      = (const float*)d_in[4];
    const float* bk      = (const float*)d_in[5];
    const float* Wv      = (const float*)d_in[6];
    const float* bv      = (const float*)d_in[7];
    const float* Wo      = (const float*)d_in[8];
    const float* bo      = (const float*)d_in[9];
    const float* Wg      = (const float*)d_in[10];
    const float* bg      = (const float*)d_in[11];
    const float* g_q     = (const float*)d_in[12];
    const float* beta_q  = (const float*)d_in[13];
    const float* g_kv    = (const float*)d_in[14];
    const float* beta_kv = (const float*)d_in[15];
    float* out = (float*)d_out;
    const float* WgB = Wg + (size_t)DD * DD;

    float *pLNs, *pWqk, *pu, *pLNa, *pWvo, *pWvg, *pbvo, *pbvg, *pctxo, *pG, *pwb;
    cudaGetSymbolAddress((void**)&pLNs,  d_LNs);
    cudaGetSymbolAddress((void**)&pWqk,  d_Wqk);
    cudaGetSymbolAddress((void**)&pu,    d_u);
    cudaGetSymbolAddress((void**)&pLNa,  d_LNa);
    cudaGetSymbolAddress((void**)&pWvo,  d_Wvo);
    cudaGetSymbolAddress((void**)&pWvg,  d_Wvg);
    cudaGetSymbolAddress((void**)&pbvo,  d_bvo);
    cudaGetSymbolAddress((void**)&pbvg,  d_bvg);
    cudaGetSymbolAddress((void**)&pctxo, d_ctxo);
    cudaGetSymbolAddress((void**)&pG,    d_G);
    cudaGetSymbolAddress((void**)&pwb,   d_wb);

    // create streams/events once (host resources only; no device allocation)
    static cudaStream_t sB = 0, sC = 0;
    static cudaEvent_t evStart = 0, evWqk = 0, evSide = 0, evAttn = 0, evC = 0;
    if (!sB) {
        cudaStreamCreateWithFlags(&sB, cudaStreamNonBlocking);
        cudaStreamCreateWithFlags(&sC, cudaStreamNonBlocking);
        cudaEventCreateWithFlags(&evStart, cudaEventDisableTiming);
        cudaEventCreateWithFlags(&evWqk,   cudaEventDisableTiming);
        cudaEventCreateWithFlags(&evSide,  cudaEventDisableTiming);
        cudaEventCreateWithFlags(&evAttn,  cudaEventDisableTiming);
        cudaEventCreateWithFlags(&evC,     cudaEventDisableTiming);
    }

    dim3 gg(DD / 64, 512 / 32);   // 8 x 16 = 128 blocks
    cudaStream_t s0 = 0;          // legacy default stream (captured by harness)

    // ---- fork side stream (weight-only branch) ----
    cudaEventRecord(evStart, s0);
    cudaStreamWaitEvent(sB, evStart, 0);

    k_bias_prep<<<DD, 128, 0, sB>>>(Wk, bq, Wq, bk);                         // wb, wqbk, bqbk
    k_gemm<1, 0><<<gg, 128, 0, sB>>>(Wq, Wk, nullptr, pWqk, nullptr);        // Wqk = Wq @ Wk^T
    cudaEventRecord(evWqk, sB);
    k_gemm<0, 0><<<gg, 128, 0, sB>>>(Wv, Wo, nullptr, pWvo, nullptr);        // Wvo = Wv @ Wo
    k_bvo<<<4, 128, 0, sB>>>(bv, bo, Wo);                                    // bvo
    k_gemm<0, 0><<<gg, 128, 0, sB>>>(pWvo, WgB, nullptr, pWvg, nullptr);     // Wvg = Wvo @ WgB
    k_bvg<<<4, 128, 0, sB>>>(bg, WgB);                                       // bvg
    k_gemm<0, 1><<<gg, 128, 0, sB>>>(sent, Wg, pbvg, pG, nullptr);           // Gtop2 = sent@WgT + bvg
    cudaEventRecord(evSide, sB);

    // ---- main chain ----
    k_ln_sent<<<BB, 128, 0, s0>>>(sent, g_q, beta_q);                        // LNs
    cudaStreamWaitEvent(s0, evWqk, 0);
    k_gemm<0, 1><<<gg, 128, 0, s0>>>(pLNs, pWqk, pwb, pu, nullptr);          // u = LNs@Wqk + wb
    k_prep<<<BB, 128, 0, s0>>>(g_kv, beta_kv);                               // gqk, c1, c2
    k_attn<<<BB, 256, 0, s0>>>(price, g_kv, beta_kv, out + (size_t)BB * DD); // attn + LNa
    cudaEventRecord(evAttn, s0);

    // ---- parallel post-attention GEMMs ----
    cudaStreamWaitEvent(sC, evAttn, 0);
    cudaStreamWaitEvent(sC, evSide, 0);
    k_gemm<0, 1><<<gg, 128, 0, sC>>>(pLNa, pWvo, pbvo, pctxo, nullptr);      // ctxo = LNa@Wvo + bvo
    cudaEventRecord(evC, sC);

    cudaStreamWaitEvent(s0, evSide, 0);
    k_gemm<0, 2><<<gg, 128, 0, s0>>>(pLNa, pWvg, nullptr, pG, pG);           // G = Gtop2 + LNa@Wvg

    cudaStreamWaitEvent(s0, evC, 0);
    k_fuse<<<(BB * DD) / 256, 256, 0, s0>>>(sent, out);                      // final fuse
}

// round 5
// speedup vs baseline: 1.9810x; 1.9810x over previous
#include <cuda_runtime.h>

#define BB 512
#define SS 512
#define DD 512
#define LN_EPS 1e-5f
#define INV_SCALE 0.125f   // 1/sqrt(64)

// ---------------- scratch ----------------
__device__ float d_LNs[BB*DD];    // LN(sentiment)
__device__ float d_Wqk[DD*DD];    // Wq @ Wk^T
__device__ float d_u[BB*DD];      // LNs @ Wqk + wb
__device__ float d_gqk[BB*DD];    // g_kv * u / 8
__device__ float d_c1[BB];
__device__ float d_c2[BB];
__device__ float d_LNa[BB*DD];    // attn-weighted LN_kv vector
__device__ float d_Wvo[DD*DD];    // Wv @ Wo
__device__ float d_bvo[DD];       // bv @ Wo + bo
__device__ float d_ctxo[BB*DD];   // context after Wo
__device__ float d_G[BB*DD];      // gate top half (sent@WgT + bg)
__device__ float d_wb[DD];        // bq @ Wk^T
__device__ float d_wqbk[DD];      // Wq @ bk
__device__ float d_bqbk;          // bq . bk

// ---------------- block reductions (128 threads) ----------------
__device__ __forceinline__ void bred2_128(float& a, float& b) {
#pragma unroll
    for (int o = 16; o; o >>= 1) {
        a += __shfl_xor_sync(0xffffffffu, a, o);
        b += __shfl_xor_sync(0xffffffffu, b, o);
    }
    __shared__ float sa[4], sb[4];
    int w = threadIdx.x >> 5;
    if ((threadIdx.x & 31) == 0) { sa[w] = a; sb[w] = b; }
    __syncthreads();
    a = sa[0] + sa[1] + sa[2] + sa[3];
    b = sb[0] + sb[1] + sb[2] + sb[3];
}

__device__ __forceinline__ void bred3_128(float& a, float& b, float& c) {
#pragma unroll
    for (int o = 16; o; o >>= 1) {
        a += __shfl_xor_sync(0xffffffffu, a, o);
        b += __shfl_xor_sync(0xffffffffu, b, o);
        c += __shfl_xor_sync(0xffffffffu, c, o);
    }
    __shared__ float sa[4], sb[4], sc[4];
    int w = threadIdx.x >> 5;
    if ((threadIdx.x & 31) == 0) { sa[w] = a; sb[w] = b; sc[w] = c; }
    __syncthreads();
    a = sa[0] + sa[1] + sa[2] + sa[3];
    b = sb[0] + sb[1] + sb[2] + sb[3];
    c = sc[0] + sc[1] + sc[2] + sc[3];
}

// ---------------- LN of sentiment ----------------
__global__ void k_ln_sent(const float* __restrict__ sent,
                          const float* __restrict__ g, const float* __restrict__ be) {
    int b = blockIdx.x, t = threadIdx.x;
    const float4* row = (const float4*)(sent + (size_t)b * DD);
    float4 x = row[t];
    float s = x.x + x.y + x.z + x.w;
    float ss = fmaf(x.x, x.x, fmaf(x.y, x.y, fmaf(x.z, x.z, x.w * x.w)));
    bred2_128(s, ss);
    float m = s * (1.0f / DD);
    float var = ss * (1.0f / DD) - m * m;
    float r = rsqrtf(var + LN_EPS);
    float4 gg = ((const float4*)g)[t];
    float4 bb = ((const float4*)be)[t];
    float4 o;
    o.x = (x.x - m) * r * gg.x + bb.x;
    o.y = (x.y - m) * r * gg.y + bb.y;
    o.z = (x.z - m) * r * gg.z + bb.z;
    o.w = (x.w - m) * r * gg.w + bb.w;
    ((float4*)(d_LNs + (size_t)b * DD))[t] = o;
}

// ---------------- weight-side bias matvecs ----------------
__global__ void k_bias_prep(const float* __restrict__ Wk, const float* __restrict__ bq,
                            const float* __restrict__ Wq, const float* __restrict__ bk) {
    int e = blockIdx.x, t = threadIdx.x;
    float a = 0.f, b2 = 0.f, c = 0.f;
    for (int d = t; d < DD; d += 128) {
        a  = fmaf(Wk[(size_t)e * DD + d], bq[d], a);
        b2 = fmaf(Wq[(size_t)e * DD + d], bk[d], b2);
        c  = fmaf(bq[d], bk[d], c);
    }
    bred3_128(a, b2, c);
    if (t == 0) {
        d_wb[e] = a;
        d_wqbk[e] = b2;
        if (e == 0) d_bqbk = c;
    }
}

// ---------------- per-batch score constants ----------------
__global__ void k_prep(const float* __restrict__ g_kv, const float* __restrict__ beta_kv) {
    int b = blockIdx.x, t = threadIdx.x;
    float4 u4  = ((const float4*)(d_u   + (size_t)b * DD))[t];
    float4 ln4 = ((const float4*)(d_LNs + (size_t)b * DD))[t];
    float4 g4  = ((const float4*)g_kv)[t];
    float4 be4 = ((const float4*)beta_kv)[t];
    float4 wq4 = ((const float4*)d_wqbk)[t];
    float4 gq;
    gq.x = g4.x * u4.x * INV_SCALE;
    gq.y = g4.y * u4.y * INV_SCALE;
    gq.z = g4.z * u4.z * INV_SCALE;
    gq.w = g4.w * u4.w * INV_SCALE;
    ((float4*)(d_gqk + (size_t)b * DD))[t] = gq;
    float c1 = gq.x + gq.y + gq.z + gq.w;
    float c2 = fmaf(be4.x, u4.x, fmaf(be4.y, u4.y, fmaf(be4.z, u4.z, be4.w * u4.w)))
             + fmaf(ln4.x, wq4.x, fmaf(ln4.y, wq4.y, fmaf(ln4.z, wq4.z, ln4.w * wq4.w)));
    bred2_128(c1, c2);
    if (t == 0) {
        d_c1[b] = c1;
        d_c2[b] = (c2 + d_bqbk) * INV_SCALE;
    }
}

// ---------------- fused LN + scores + online softmax + weighted accum ----------------
__global__ void __launch_bounds__(256) k_attn(const float* __restrict__ price,
                                              const float* __restrict__ g_kv,
                                              const float* __restrict__ beta_kv,
                                              float* __restrict__ attn_out) {
    int b = blockIdx.x;
    int t = threadIdx.x, w = t >> 5, l = t & 31;

    __shared__ float s_sc[SS];
    __shared__ float s_wm[8], s_wz[8], s_wt[8];
    __shared__ float s_y[8][DD];

    const float4* gq4 = (const float4*)(d_gqk + (size_t)b * DD);
    float4 gq[4];
#pragma unroll
    for (int i = 0; i < 4; i++) gq[i] = gq4[l + 32 * i];
    const float c1 = d_c1[b], c2 = d_c2[b];

    float yac[4][4];
#pragma unroll
    for (int i = 0; i < 4; i++)
#pragma unroll
        for (int j = 0; j < 4; j++) yac[i][j] = 0.f;

    float M = -1e30f, Z = 0.f, T = 0.f;

    const float4* xr = (const float4*)(price + ((size_t)b * SS + (size_t)w * 64) * DD);
    float4 p0 = __ldcs(xr + l), p1 = __ldcs(xr + l + 32),
           p2 = __ldcs(xr + l + 64), p3 = __ldcs(xr + l + 96);

    for (int s = 0; s < 64; s++) {
        float4 x0 = p0, x1 = p1, x2 = p2, x3 = p3;
        if (s < 63) {
            xr += 128;
            p0 = __ldcs(xr + l);      p1 = __ldcs(xr + l + 32);
            p2 = __ldcs(xr + l + 64); p3 = __ldcs(xr + l + 96);
        }

        float sx = 0.f, sxx = 0.f, sxg = 0.f;
#define ACC4(v, g) do { \
        sx += v.x + v.y + v.z + v.w; \
        sxx = fmaf(v.x, v.x, fmaf(v.y, v.y, fmaf(v.z, v.z, fmaf(v.w, v.w, sxx)))); \
        sxg = fmaf(v.x, g.x, fmaf(v.y, g.y, fmaf(v.z, g.z, fmaf(v.w, g.w, sxg)))); } while (0)
        ACC4(x0, gq[0]); ACC4(x1, gq[1]); ACC4(x2, gq[2]); ACC4(x3, gq[3]);
#undef ACC4

#pragma unroll
        for (int o = 16; o; o >>= 1) {
            sx  += __shfl_xor_sync(0xffffffffu, sx, o);
            sxx += __shfl_xor_sync(0xffffffffu, sxx, o);
            sxg += __shfl_xor_sync(0xffffffffu, sxg, o);
        }
        float m = sx * (1.0f / DD);
        float var = sxx * (1.0f / DD) - m * m;
        float r = rsqrtf(var + LN_EPS);
        float sc = fmaf(r, sxg - m * c1, c2);
        if (l == 0) s_sc[w * 64 + s] = sc;

        float wgt;
        if (sc > M) {   // warp-uniform after butterfly
            float corr = __expf(M - sc);
            Z *= corr; T *= corr;
#pragma unroll
            for (int i = 0; i < 4; i++)
#pragma unroll
                for (int j = 0; j < 4; j++) yac[i][j] *= corr;
            M = sc;
            wgt = 1.0f;
        } else {
            wgt = __expf(sc - M);
        }
        Z += wgt;
        float cw = wgt * r;
        T = fmaf(cw, m, T);
        yac[0][0] = fmaf(cw, x0.x, yac[0][0]); yac[0][1] = fmaf(cw, x0.y, yac[0][1]);
        yac[0][2] = fmaf(cw, x0.z, yac[0][2]); yac[0][3] = fmaf(cw, x0.w, yac[0][3]);
        yac[1][0] = fmaf(cw, x1.x, yac[1][0]); yac[1][1] = fmaf(cw, x1.y, yac[1][1]);
        yac[1][2] = fmaf(cw, x1.z, yac[1][2]); yac[1][3] = fmaf(cw, x1.w, yac[1][3]);
        yac[2][0] = fmaf(cw, x2.x, yac[2][0]); yac[2][1] = fmaf(cw, x2.y, yac[2][1]);
        yac[2][2] = fmaf(cw, x2.z, yac[2][2]); yac[2][3] = fmaf(cw, x2.w, yac[2][3]);
        yac[3][0] = fmaf(cw, x3.x, yac[3][0]); yac[3][1] = fmaf(cw, x3.y, yac[3][1]);
        yac[3][2] = fmaf(cw, x3.z, yac[3][2]); yac[3][3] = fmaf(cw, x3.w, yac[3][3]);
    }

    if (l == 0) { s_wm[w] = M; s_wz[w] = Z; s_wt[w] = T; }
    __syncthreads();

    float gM = s_wm[0];
#pragma unroll
    for (int i = 1; i < 8; i++) gM = fmaxf(gM, s_wm[i]);
    float Zg = 0.f, Tg = 0.f;
#pragma unroll
    for (int i = 0; i < 8; i++) {
        float e = __expf(s_wm[i] - gM);
        Zg = fmaf(s_wz[i], e, Zg);
        Tg = fmaf(s_wt[i], e, Tg);
    }
    float myf = __expf(M - gM);
#pragma unroll
    for (int i = 0; i < 4; i++) {
        float4 v = make_float4(yac[i][0] * myf, yac[i][1] * myf, yac[i][2] * myf, yac[i][3] * myf);
        *(float4*)&s_y[w][4 * (l + 32 * i)] = v;
    }
    __syncthreads();

    float invZ = 1.0f / Zg;
    float tvv = Tg * invZ;
    for (int e = t; e < DD; e += 256) {
        float acc = 0.f;
#pragma unroll
        for (int w2 = 0; w2 < 8; w2++) acc += s_y[w2][e];
        d_LNa[(size_t)b * DD + e] = fmaf(g_kv[e], acc * invZ - tvv, beta_kv[e]);
    }
    for (int s = t; s < SS; s += 256)
        attn_out[(size_t)b * SS + s] = __expf(s_sc[s] - gM) * invZ;
}

// ---------------- bvo: init with bo, then K-split partial sums via atomics ----------------
__global__ void k_bvo_init(const float* __restrict__ bo) {
    int d = blockIdx.x * 128 + threadIdx.x;
    d_bvo[d] = bo[d];
}
__global__ void k_bvo_part(const float* __restrict__ bv, const float* __restrict__ Wo) {
    int d = blockIdx.x * 128 + threadIdx.x;
    int e0 = blockIdx.y * 32;
    float a0 = 0.f, a1 = 0.f, a2 = 0.f, a3 = 0.f;
#pragma unroll
    for (int e = 0; e < 32; e += 4) {
        a0 = fmaf(bv[e0 + e + 0], Wo[(size_t)(e0 + e + 0) * DD + d], a0);
        a1 = fmaf(bv[e0 + e + 1], Wo[(size_t)(e0 + e + 1) * DD + d], a1);
        a2 = fmaf(bv[e0 + e + 2], Wo[(size_t)(e0 + e + 2) * DD + d], a2);
        a3 = fmaf(bv[e0 + e + 3], Wo[(size_t)(e0 + e + 3) * DD + d], a3);
    }
    atomicAdd(&d_bvo[d], a0 + a1 + a2 + a3);
}

// ---------------- SGEMM: 32x64 tile, 128 threads, 4x4/thread, double-buffered ----------------
// EPI: 0 = store; 1 = store + bias[col]; 2 = gate-fuse (bias=Gtop matrix, X1=ctxo, X2=sent)
template <int TRANSB, int EPI>
__global__ void __launch_bounds__(128) k_gemm(const float* __restrict__ A,
                                              const float* __restrict__ Bm,
                                              const float* __restrict__ bias,
                                              float* __restrict__ C,
                                              const float* __restrict__ X1,
                                              const float* __restrict__ X2) {
    __shared__ float As[2][32][36];
    __shared__ float Bs[2][32][68];
    const int t = threadIdx.x;
    const int tx = t & 15, ty = t >> 4;
    const int m0 = blockIdx.y * 32, n0 = blockIdx.x * 64;

    const int arA = t >> 3, aq = t & 7;
    const float* Abase = A + (size_t)(m0 + arA) * DD + aq * 4;
    const int brB = t >> 4, bq = t & 15;
    const int nrB = t >> 3;
    const float* Bbase = TRANSB ? (Bm + (size_t)(n0 + nrB) * DD + aq * 4)
                                : (Bm + (size_t)brB * DD + n0 + bq * 4);

    float acc[4][4];
#pragma unroll
    for (int i = 0; i < 4; i++)
#pragma unroll
        for (int j = 0; j < 4; j++) acc[i][j] = 0.f;

    float4 aP[2], bP[4];

    aP[0] = *(const float4*)(Abase);
    aP[1] = *(const float4*)(Abase + 16 * DD);
#pragma unroll
    for (int i = 0; i < 4; i++)
        bP[i] = TRANSB ? *(const float4*)(Bbase + (size_t)(16 * i) * DD)
                       : *(const float4*)(Bbase + (size_t)(8 * i) * DD);

    {
        As[0][aq * 4 + 0][arA] = aP[0].x; As[0][aq * 4 + 1][arA] = aP[0].y;
        As[0][aq * 4 + 2][arA] = aP[0].z; As[0][aq * 4 + 3][arA] = aP[0].w;
        As[0][aq * 4 + 0][arA + 16] = aP[1].x; As[0][aq * 4 + 1][arA + 16] = aP[1].y;
        As[0][aq * 4 + 2][arA + 16] = aP[1].z; As[0][aq * 4 + 3][arA + 16] = aP[1].w;
        if (TRANSB) {
#pragma unroll
            for (int i = 0; i < 4; i++) {
                Bs[0][aq * 4 + 0][nrB + 16 * i] = bP[i].x;
                Bs[0][aq * 4 + 1][nrB + 16 * i] = bP[i].y;
                Bs[0][aq * 4 + 2][nrB + 16 * i] = bP[i].z;
                Bs[0][aq * 4 + 3][nrB + 16 * i] = bP[i].w;
            }
        } else {
#pragma unroll
            for (int i = 0; i < 4; i++)
                *(float4*)&Bs[0][brB + 8 * i][bq * 4] = bP[i];
        }
    }
    __syncthreads();

    int buf = 0;
#pragma unroll 1
    for (int kt = 0; kt < 16; kt++) {
        if (kt < 15) {
            int ko = (kt + 1) * 32;
            aP[0] = *(const float4*)(Abase + ko);
            aP[1] = *(const float4*)(Abase + 16 * DD + ko);
#pragma unroll
            for (int i = 0; i < 4; i++)
                bP[i] = TRANSB ? *(const float4*)(Bbase + (size_t)(16 * i) * DD + ko)
                               : *(const float4*)(Bbase + (size_t)(ko + 8 * i) * DD);
        }
#pragma unroll
        for (int k = 0; k < 32; k++) {
            float4 a4 = *(const float4*)&As[buf][k][ty * 4];
            float4 b4 = *(const float4*)&Bs[buf][k][tx * 4];
            float ar[4] = {a4.x, a4.y, a4.z, a4.w};
            float br[4] = {b4.x, b4.y, b4.z, b4.w};
#pragma unroll
            for (int i = 0; i < 4; i++)
#pragma unroll
                for (int j = 0; j < 4; j++) acc[i][j] = fmaf(ar[i], br[j], acc[i][j]);
        }
        if (kt < 15) {
            int nb = buf ^ 1;
            As[nb][aq * 4 + 0][arA] = aP[0].x; As[nb][aq * 4 + 1][arA] = aP[0].y;
            As[nb][aq * 4 + 2][arA] = aP[0].z; As[nb][aq * 4 + 3][arA] = aP[0].w;
            As[nb][aq * 4 + 0][arA + 16] = aP[1].x; As[nb][aq * 4 + 1][arA + 16] = aP[1].y;
            As[nb][aq * 4 + 2][arA + 16] = aP[1].z; As[nb][aq * 4 + 3][arA + 16] = aP[1].w;
            if (TRANSB) {
#pragma unroll
                for (int i = 0; i < 4; i++) {
                    Bs[nb][aq * 4 + 0][nrB + 16 * i] = bP[i].x;
                    Bs[nb][aq * 4 + 1][nrB + 16 * i] = bP[i].y;
                    Bs[nb][aq * 4 + 2][nrB + 16 * i] = bP[i].z;
                    Bs[nb][aq * 4 + 3][nrB + 16 * i] = bP[i].w;
                }
            } else {
#pragma unroll
                for (int i = 0; i < 4; i++)
                    *(float4*)&Bs[nb][brB + 8 * i][bq * 4] = bP[i];
            }
        }
        __syncthreads();
        buf ^= 1;
    }

#pragma unroll
    for (int i = 0; i < 4; i++) {
        int row = m0 + ty * 4 + i;
        float* cp = C + (size_t)row * DD + n0 + tx * 4;
        float4 v = make_float4(acc[i][0], acc[i][1], acc[i][2], acc[i][3]);
        if (EPI == 1) {
            const float* bp = bias + n0 + tx * 4;
            v.x += bp[0]; v.y += bp[1]; v.z += bp[2]; v.w += bp[3];
        }
        if (EPI == 2) {
            const float4 gt = *(const float4*)(bias + (size_t)row * DD + n0 + tx * 4);
            const float4 cx = *(const float4*)(X1 + (size_t)row * DD + n0 + tx * 4);
            const float4 sn = *(const float4*)(X2 + (size_t)row * DD + n0 + tx * 4);
            float ax = 1.0f / (1.0f + __expf(-(gt.x + v.x)));
            float ay = 1.0f / (1.0f + __expf(-(gt.y + v.y)));
            float az = 1.0f / (1.0f + __expf(-(gt.z + v.z)));
            float aw = 1.0f / (1.0f + __expf(-(gt.w + v.w)));
            v.x = fmaf(ax, cx.x - sn.x, sn.x);
            v.y = fmaf(ay, cx.y - sn.y, sn.y);
            v.z = fmaf(az, cx.z - sn.z, sn.z);
            v.w = fmaf(aw, cx.w - sn.w, sn.w);
        }
        *(float4*)cp = v;
    }
}

// ---------------- launch ----------------
extern "C" void kernel_launch(void* const* d_in, const int* in_sizes, int n_in,
                              void* d_out, int out_size) {
    const float* sent    = (const float*)d_in[0];
    const float* price   = (const float*)d_in[1];
    const float* Wq      = (const float*)d_in[2];
    const float* bq      = (const float*)d_in[3];
    const float* Wk      = (const float*)d_in[4];
    const float* bk      = (const float*)d_in[5];
    const float* Wv      = (const float*)d_in[6];
    const float* bv      = (const float*)d_in[7];
    const float* Wo      = (const float*)d_in[8];
    const float* bo      = (const float*)d_in[9];
    const float* Wg      = (const float*)d_in[10];
    const float* bg      = (const float*)d_in[11];
    const float* g_q     = (const float*)d_in[12];
    const float* beta_q  = (const float*)d_in[13];
    const float* g_kv    = (const float*)d_in[14];
    const float* beta_kv = (const float*)d_in[15];
    float* out = (float*)d_out;
    const float* WgB = Wg + (size_t)DD * DD;

    float *pLNs, *pWqk, *pu, *pLNa, *pWvo, *pbvo, *pctxo, *pG, *pwb;
    cudaGetSymbolAddress((void**)&pLNs,  d_LNs);
    cudaGetSymbolAddress((void**)&pWqk,  d_Wqk);
    cudaGetSymbolAddress((void**)&pu,    d_u);
    cudaGetSymbolAddress((void**)&pLNa,  d_LNa);
    cudaGetSymbolAddress((void**)&pWvo,  d_Wvo);
    cudaGetSymbolAddress((void**)&pbvo,  d_bvo);
    cudaGetSymbolAddress((void**)&pctxo, d_ctxo);
    cudaGetSymbolAddress((void**)&pG,    d_G);
    cudaGetSymbolAddress((void**)&pwb,   d_wb);

    static cudaStream_t sB = 0;
    static cudaEvent_t evStart = 0, evWqk = 0, evSide = 0;
    if (!sB) {
        cudaStreamCreateWithFlags(&sB, cudaStreamNonBlocking);
        cudaEventCreateWithFlags(&evStart, cudaEventDisableTiming);
        cudaEventCreateWithFlags(&evWqk,   cudaEventDisableTiming);
        cudaEventCreateWithFlags(&evSide,  cudaEventDisableTiming);
    }

    dim3 gg(DD / 64, 512 / 32);   // 8 x 16 = 128 blocks
    cudaStream_t s0 = 0;

    // ---- fork side stream (light weight-only branch) ----
    cudaEventRecord(evStart, s0);
    cudaStreamWaitEvent(sB, evStart, 0);

    k_bias_prep<<<DD, 128, 0, sB>>>(Wk, bq, Wq, bk);                          // wb, wqbk, bqbk
    k_gemm<1, 0><<<gg, 128, 0, sB>>>(Wq, Wk, nullptr, pWqk, nullptr, nullptr); // Wqk = Wq @ Wk^T
    cudaEventRecord(evWqk, sB);
    k_gemm<0, 0><<<gg, 128, 0, sB>>>(Wv, Wo, nullptr, pWvo, nullptr, nullptr); // Wvo = Wv @ Wo
    k_bvo_init<<<4, 128, 0, sB>>>(bo);
    k_bvo_part<<<dim3(4, 16), 128, 0, sB>>>(bv, Wo);                          // bvo (fast)
    k_gemm<0, 1><<<gg, 128, 0, sB>>>(sent, Wg, bg, pG, nullptr, nullptr);     // Gtop = sent@WgT + bg
    cudaEventRecord(evSide, sB);

    // ---- main chain ----
    k_ln_sent<<<BB, 128, 0, s0>>>(sent, g_q, beta_q);                         // LNs
    cudaStreamWaitEvent(s0, evWqk, 0);
    k_gemm<0, 1><<<gg, 128, 0, s0>>>(pLNs, pWqk, pwb, pu, nullptr, nullptr);  // u = LNs@Wqk + wb
    k_prep<<<BB, 128, 0, s0>>>(g_kv, beta_kv);                                // gqk, c1, c2
    k_attn<<<BB, 256, 0, s0>>>(price, g_kv, beta_kv, out + (size_t)BB * DD);  // attn + LNa

    // ---- post-attention (needs side branch done) ----
    cudaStreamWaitEvent(s0, evSide, 0);
    k_gemm<0, 1><<<gg, 128, 0, s0>>>(pLNa, pWvo, pbvo, pctxo, nullptr, nullptr); // ctxo = LNa@Wvo + bvo
    k_gemm<0, 2><<<gg, 128, 0, s0>>>(pctxo, WgB, pG, out, pctxo, sent);          // gate-fuse -> out
}